// round 5
// baseline (speedup 1.0000x reference)
#include <cuda_runtime.h>
#include <math.h>

// ---------------- problem constants ----------------
#define BATCH   2
#define SEQLEN  2048
#define DMODEL  1024
#define DINNER  2048
#define DSTATE  16
#define DTRANK  64
#define NTOK    (BATCH * SEQLEN)           // 4096
#define XPW     (DTRANK + 2 * DSTATE)      // 96

// ---------------- scratch (device globals; no cudaMalloc allowed) ----------------
__device__ float g_xz[NTOK * 2 * DINNER];        // (4096, 4096): xi cols [0,2048), z cols [2048,4096)
__device__ float g_xs[NTOK * DINNER];            // conv+silu output
__device__ float g_xp[NTOK * XPW];               // dt | B | C
__device__ float g_delta[NTOK * DINNER];         // softplus(dt @ W_dt + b_dt)
__device__ float g_y[NTOK * DINNER];             // gated scan output
__device__ float g_part[8 * NTOK * XPW];         // split-K partials for G2

// ---------------- fp32 tiled GEMM: C(MxN) = A(MxK) @ B(KxN) ----------------
// BM=BN=128, BK=8, 256 threads, 8x8 per thread. M must be a multiple of 128,
// Kslice a multiple of 8; N bounds-checked. EPI==1: C = softplus(acc + bias[col]).
template <int EPI>
__global__ void __launch_bounds__(256, 2)
sgemm128(const float* __restrict__ A, int lda,
         const float* __restrict__ B, int ldb,
         float* __restrict__ C, int ldc,
         int N, int Kslice,
         const float* __restrict__ bias,
         long long c_slice_stride)
{
    __shared__ float sA[8][128];
    __shared__ float sB[8][128];

    const int bm = blockIdx.y * 128;
    const int bn = blockIdx.x * 128;
    const int k0 = blockIdx.z * Kslice;
    C += (long long)blockIdx.z * c_slice_stride;

    const int tid  = threadIdx.x;
    const int arow = tid >> 1;
    const int akc  = (tid & 1) << 2;
    const int brow = tid >> 5;
    const int bcol = (tid & 31) << 2;
    const int tx   = tid & 15;
    const int ty   = tid >> 4;

    float acc[8][8];
#pragma unroll
    for (int i = 0; i < 8; i++)
#pragma unroll
        for (int j = 0; j < 8; j++) acc[i][j] = 0.f;

    const float* Aptr = A + (size_t)(bm + arow) * lda + k0 + akc;
    const float* Bptr = B + (size_t)(k0 + brow) * ldb + bn + bcol;
    const bool bok = (bn + bcol) < N;

    for (int kk = 0; kk < Kslice; kk += 8) {
        float4 av = *reinterpret_cast<const float4*>(Aptr);
        Aptr += 8;
        float4 bv = make_float4(0.f, 0.f, 0.f, 0.f);
        if (bok) bv = *reinterpret_cast<const float4*>(Bptr);
        Bptr += (size_t)8 * ldb;

        sA[akc + 0][arow] = av.x;
        sA[akc + 1][arow] = av.y;
        sA[akc + 2][arow] = av.z;
        sA[akc + 3][arow] = av.w;
        *reinterpret_cast<float4*>(&sB[brow][bcol]) = bv;
        __syncthreads();

#pragma unroll
        for (int p = 0; p < 8; p++) {
            float4 a0 = *reinterpret_cast<const float4*>(&sA[p][ty * 8]);
            float4 a1 = *reinterpret_cast<const float4*>(&sA[p][ty * 8 + 4]);
            float4 b0 = *reinterpret_cast<const float4*>(&sB[p][tx * 8]);
            float4 b1 = *reinterpret_cast<const float4*>(&sB[p][tx * 8 + 4]);
            float ra[8] = {a0.x, a0.y, a0.z, a0.w, a1.x, a1.y, a1.z, a1.w};
            float rb[8] = {b0.x, b0.y, b0.z, b0.w, b1.x, b1.y, b1.z, b1.w};
#pragma unroll
            for (int i = 0; i < 8; i++)
#pragma unroll
                for (int j = 0; j < 8; j++)
                    acc[i][j] = fmaf(ra[i], rb[j], acc[i][j]);
        }
        __syncthreads();
    }

#pragma unroll
    for (int i = 0; i < 8; i++) {
        const int row = bm + ty * 8 + i;
#pragma unroll
        for (int j = 0; j < 8; j++) {
            const int col = bn + tx * 8 + j;
            if (col < N) {
                float v = acc[i][j];
                if (EPI == 1) {
                    v += bias[col];
                    v = (v > 20.f) ? v : log1pf(expf(v));
                }
                C[(size_t)row * ldc + col] = v;
            }
        }
    }
}

// ---------------- depthwise causal conv (k=4) + SiLU ----------------
__global__ void conv_silu_kernel(const float* __restrict__ xz,
                                 const float* __restrict__ cw,
                                 const float* __restrict__ cb,
                                 float* __restrict__ xs)
{
    const int idx = blockIdx.x * blockDim.x + threadIdx.x;
    if (idx >= NTOK * DINNER) return;
    const int d   = idx & (DINNER - 1);
    const int tok = idx >> 11;                 // DINNER == 2048
    const int l   = tok & (SEQLEN - 1);

    float acc = cb[d];
    const float w0 = cw[d * 4 + 0];
    const float w1 = cw[d * 4 + 1];
    const float w2 = cw[d * 4 + 2];
    const float w3 = cw[d * 4 + 3];
    if (l >= 3) acc += w0 * xz[(size_t)(tok - 3) * (2 * DINNER) + d];
    if (l >= 2) acc += w1 * xz[(size_t)(tok - 2) * (2 * DINNER) + d];
    if (l >= 1) acc += w2 * xz[(size_t)(tok - 1) * (2 * DINNER) + d];
    acc += w3 * xz[(size_t)tok * (2 * DINNER) + d];

    xs[idx] = acc / (1.f + __expf(-acc));      // SiLU
}

// ---------------- split-K reduction (8 slices) ----------------
__global__ void reduce8_kernel(const float* __restrict__ part,
                               float* __restrict__ out, int len)
{
    const int i = blockIdx.x * blockDim.x + threadIdx.x;
    if (i >= len) return;
    float s = 0.f;
#pragma unroll
    for (int k = 0; k < 8; k++) s += part[(size_t)k * len + i];
    out[i] = s;
}

// ---------------- selective scan + skip + gate ----------------
// Lane-per-state: 16 lanes = 16 states of one channel; 2 channels per warp.
// Block = 128 threads = 8 channels of one batch. Grid = (DINNER/8, BATCH).
__global__ void __launch_bounds__(128)
scan_kernel(const float* __restrict__ delta,
            const float* __restrict__ xs,
            const float* __restrict__ xp,
            const float* __restrict__ xz,
            const float* __restrict__ A_log,
            const float* __restrict__ Dpar,
            float* __restrict__ y)
{
    const int TT = 128;
    __shared__ float sB[TT][16];
    __shared__ float sC[TT][16];
    __shared__ float sd[TT][8];
    __shared__ float sx[TT][8];
    __shared__ float sz[TT][8];
    __shared__ float so[TT][8];

    const int b    = blockIdx.y;
    const int d0   = blockIdx.x * 8;
    const int tid  = threadIdx.x;
    const int lane = tid & 31;
    const int warp = tid >> 5;
    const int grp  = lane >> 4;
    const int n    = lane & 15;
    const int ch   = warp * 2 + grp;     // local channel 0..7
    const int d    = d0 + ch;

    const float An = -__expf(A_log[d * DSTATE + n]);
    const float Dd = Dpar[d];
    float h = 0.f;

    for (int l0 = 0; l0 < SEQLEN; l0 += TT) {
        // stage B/C (per-batch, shared by all channels)
        for (int i = tid; i < TT * 16; i += 128) {
            const int t = i >> 4, nn = i & 15;
            const float* row = xp + (size_t)(b * SEQLEN + l0 + t) * XPW;
            sB[t][nn] = row[DTRANK + nn];
            sC[t][nn] = row[DTRANK + DSTATE + nn];
        }
        // stage delta / x / silu(z)
        for (int i = tid; i < TT * 8; i += 128) {
            const int t = i >> 3, c = i & 7;
            const size_t tok = (size_t)(b * SEQLEN + l0 + t);
            sd[t][c] = delta[tok * DINNER + d0 + c];
            sx[t][c] = xs[tok * DINNER + d0 + c];
            const float zz = xz[tok * (2 * DINNER) + DINNER + d0 + c];
            sz[t][c] = zz / (1.f + __expf(-zz));
        }
        __syncthreads();

#pragma unroll 4
        for (int t = 0; t < TT; t++) {
            const float dt = sd[t][ch];
            const float xt = sx[t][ch];
            const float dA = __expf(dt * An);
            h = fmaf(dA, h, dt * xt * sB[t][n]);
            float yv = h * sC[t][n];
            yv += __shfl_xor_sync(0xffffffffu, yv, 8);
            yv += __shfl_xor_sync(0xffffffffu, yv, 4);
            yv += __shfl_xor_sync(0xffffffffu, yv, 2);
            yv += __shfl_xor_sync(0xffffffffu, yv, 1);
            if (n == 0) so[t][ch] = (yv + Dd * xt) * sz[t][ch];
        }
        __syncthreads();

        for (int i = tid; i < TT * 8; i += 128) {
            const int t = i >> 3, c = i & 7;
            y[(size_t)(b * SEQLEN + l0 + t) * DINNER + d0 + c] = so[t][c];
        }
        // next-tile 'so' writes are guarded by the post-load __syncthreads
    }
}

// ---------------- launcher ----------------
extern "C" void kernel_launch(void* const* d_in, const int* in_sizes, int n_in,
                              void* d_out, int out_size)
{
    const float* x       = (const float*)d_in[0];
    const float* W_in    = (const float*)d_in[1];
    const float* conv_w  = (const float*)d_in[2];
    const float* conv_b  = (const float*)d_in[3];
    const float* W_xproj = (const float*)d_in[4];
    const float* W_dt    = (const float*)d_in[5];
    const float* b_dt    = (const float*)d_in[6];
    const float* A_log   = (const float*)d_in[7];
    const float* Dpar    = (const float*)d_in[8];
    const float* W_out   = (const float*)d_in[9];
    float* out = (float*)d_out;

    float *xz, *xs, *xp, *delta, *y, *part;
    cudaGetSymbolAddress((void**)&xz,    g_xz);
    cudaGetSymbolAddress((void**)&xs,    g_xs);
    cudaGetSymbolAddress((void**)&xp,    g_xp);
    cudaGetSymbolAddress((void**)&delta, g_delta);
    cudaGetSymbolAddress((void**)&y,     g_y);
    cudaGetSymbolAddress((void**)&part,  g_part);

    // G1: xz = x @ W_in                       (4096 x 1024) @ (1024 x 4096)
    sgemm128<0><<<dim3((2 * DINNER) / 128, NTOK / 128, 1), 256>>>(
        x, DMODEL, W_in, 2 * DINNER, xz, 2 * DINNER,
        2 * DINNER, DMODEL, nullptr, 0);

    // depthwise causal conv + SiLU -> xs
    conv_silu_kernel<<<(NTOK * DINNER) / 256, 256>>>(xz, conv_w, conv_b, xs);

    // G2 (split-K=8): xp = xs @ W_xproj       (4096 x 2048) @ (2048 x 96)
    sgemm128<0><<<dim3(1, NTOK / 128, 8), 256>>>(
        xs, DINNER, W_xproj, XPW, part, XPW,
        XPW, DINNER / 8, nullptr, (long long)NTOK * XPW);
    reduce8_kernel<<<(NTOK * XPW + 255) / 256, 256>>>(part, xp, NTOK * XPW);

    // G3: delta = softplus(xp[:, :64] @ W_dt + b_dt)   (4096 x 64) @ (64 x 2048)
    sgemm128<1><<<dim3(DINNER / 128, NTOK / 128, 1), 256>>>(
        xp, XPW, W_dt, DINNER, delta, DINNER,
        DINNER, DTRANK, b_dt, 0);

    // selective scan + D*x skip + silu(z) gate -> y
    scan_kernel<<<dim3(DINNER / 8, BATCH), 128>>>(
        delta, xs, xp, xz, A_log, Dpar, y);

    // G4: out = y @ W_out                     (4096 x 2048) @ (2048 x 1024)
    sgemm128<0><<<dim3(DMODEL / 128, NTOK / 128, 1), 256>>>(
        y, DINNER, W_out, DMODEL, out, DMODEL,
        DMODEL, DINNER, nullptr, 0);
}

// round 6
// speedup vs baseline: 1.5171x; 1.5171x over previous
#include <cuda_runtime.h>
#include <mma.h>
#include <math.h>

using namespace nvcuda;

// ---------------- problem constants ----------------
#define BATCH   2
#define SEQLEN  2048
#define DMODEL  1024
#define DINNER  2048
#define DSTATE  16
#define DTRANK  64
#define NTOK    (BATCH * SEQLEN)           // 4096
#define XPW     (DTRANK + 2 * DSTATE)      // 96

// ---------------- scratch (device globals; no cudaMalloc allowed) ----------------
__device__ float g_xz[NTOK * 2 * DINNER];        // (4096, 4096): xi cols [0,2048), z cols [2048,4096)
__device__ float g_xs[NTOK * DINNER];            // conv+silu output
__device__ float g_xp[NTOK * XPW];               // dt | B | C
__device__ float g_delta[NTOK * DINNER];         // softplus(dt @ W_dt + b_dt)
__device__ float g_y[NTOK * DINNER];             // gated scan output
__device__ float g_part[8 * NTOK * XPW];         // split-K partials for G2

// ---------------- cp.async helpers ----------------
__device__ __forceinline__ void cp_async16(void* smem_dst, const void* gmem_src) {
    unsigned saddr = (unsigned)__cvta_generic_to_shared(smem_dst);
    asm volatile("cp.async.cg.shared.global [%0], [%1], 16;\n" :: "r"(saddr), "l"(gmem_src));
}
__device__ __forceinline__ void cp_async_commit() {
    asm volatile("cp.async.commit_group;\n" ::);
}
__device__ __forceinline__ void cp_async_wait0() {
    asm volatile("cp.async.wait_group 0;\n" ::);
}

// ---------------- TF32 tensor-core GEMM: C(MxN) = A(MxK) @ B(KxN) ----------------
// Row-major A and B. BM=BN=128, BK=16, 256 threads (8 warps), warp tile 64x32.
// M, N multiples of 128; K multiple of 16. cp.async double-buffered.
__global__ void __launch_bounds__(256)
gemm_tf32(const float* __restrict__ A, int lda,
          const float* __restrict__ B, int ldb,
          float* __restrict__ C, int ldc, int K)
{
    __shared__ float sA[2][128][24];   // 24576 B   (pad 24: 32B-aligned frag rows)
    __shared__ float sB[2][16][136];   // 17408 B   (pad 136: 32B-aligned frag rows)

    const int bm  = blockIdx.y * 128;
    const int bn  = blockIdx.x * 128;
    const int tid = threadIdx.x;
    const int warp = tid >> 5;
    const int wrow = warp >> 2;        // 0..1 -> 64 rows each
    const int wcol = warp & 3;         // 0..3 -> 32 cols each

    wmma::fragment<wmma::accumulator, 16, 16, 8, float> acc[4][2];
#pragma unroll
    for (int i = 0; i < 4; i++)
#pragma unroll
        for (int j = 0; j < 2; j++) wmma::fill_fragment(acc[i][j], 0.f);

    // per-thread load coordinates
    const int a_row0 = tid >> 2;          // + 128*? no: 1024 f4 over 2 iters
    const int a_c4   = tid & 3;
    const int b_row0 = tid >> 5;
    const int b_c4   = tid & 31;

    const int T = K >> 4;                 // K/16 tiles

    // prologue: stage tile 0 into buffer 0
    {
        const int kt = 0;
#pragma unroll
        for (int i = 0; i < 2; i++) {
            const int row = a_row0 + i * 64;
            cp_async16(&sA[0][row][a_c4 * 4],
                       A + (size_t)(bm + row) * lda + kt * 16 + a_c4 * 4);
        }
#pragma unroll
        for (int i = 0; i < 2; i++) {
            const int row = b_row0 + i * 8;
            cp_async16(&sB[0][row][b_c4 * 4],
                       B + (size_t)(kt * 16 + row) * ldb + bn + b_c4 * 4);
        }
        cp_async_commit();
    }

    for (int t = 0; t < T; t++) {
        const int s = t & 1;
        cp_async_wait0();
        __syncthreads();

        if (t + 1 < T) {
            const int kt = t + 1;
            const int s2 = s ^ 1;
#pragma unroll
            for (int i = 0; i < 2; i++) {
                const int row = a_row0 + i * 64;
                cp_async16(&sA[s2][row][a_c4 * 4],
                           A + (size_t)(bm + row) * lda + kt * 16 + a_c4 * 4);
            }
#pragma unroll
            for (int i = 0; i < 2; i++) {
                const int row = b_row0 + i * 8;
                cp_async16(&sB[s2][row][b_c4 * 4],
                           B + (size_t)(kt * 16 + row) * ldb + bn + b_c4 * 4);
            }
            cp_async_commit();
        }

#pragma unroll
        for (int ks = 0; ks < 2; ks++) {
            wmma::fragment<wmma::matrix_a, 16, 16, 8, wmma::precision::tf32, wmma::row_major> af[4];
            wmma::fragment<wmma::matrix_b, 16, 16, 8, wmma::precision::tf32, wmma::row_major> bf[2];
#pragma unroll
            for (int i = 0; i < 4; i++) {
                wmma::load_matrix_sync(af[i], &sA[s][wrow * 64 + i * 16][ks * 8], 24);
#pragma unroll
                for (int e = 0; e < af[i].num_elements; e++)
                    af[i].x[e] = wmma::__float_to_tf32(af[i].x[e]);
            }
#pragma unroll
            for (int j = 0; j < 2; j++) {
                wmma::load_matrix_sync(bf[j], &sB[s][ks * 8][wcol * 32 + j * 16], 136);
#pragma unroll
                for (int e = 0; e < bf[j].num_elements; e++)
                    bf[j].x[e] = wmma::__float_to_tf32(bf[j].x[e]);
            }
#pragma unroll
            for (int i = 0; i < 4; i++)
#pragma unroll
                for (int j = 0; j < 2; j++)
                    wmma::mma_sync(acc[i][j], af[i], bf[j], acc[i][j]);
        }
        __syncthreads();
    }

#pragma unroll
    for (int i = 0; i < 4; i++)
#pragma unroll
        for (int j = 0; j < 2; j++) {
            float* dst = C + (size_t)(bm + wrow * 64 + i * 16) * ldc
                           + bn + wcol * 32 + j * 16;
            wmma::store_matrix_sync(dst, acc[i][j], ldc, wmma::mem_row_major);
        }
}

// ---------------- fp32 tiled GEMM (kept for skinny G2 / G3) ----------------
template <int EPI>
__global__ void __launch_bounds__(256, 2)
sgemm128(const float* __restrict__ A, int lda,
         const float* __restrict__ B, int ldb,
         float* __restrict__ C, int ldc,
         int N, int Kslice,
         const float* __restrict__ bias,
         long long c_slice_stride)
{
    __shared__ float sA[8][128];
    __shared__ float sB[8][128];

    const int bm = blockIdx.y * 128;
    const int bn = blockIdx.x * 128;
    const int k0 = blockIdx.z * Kslice;
    C += (long long)blockIdx.z * c_slice_stride;

    const int tid  = threadIdx.x;
    const int arow = tid >> 1;
    const int akc  = (tid & 1) << 2;
    const int brow = tid >> 5;
    const int bcol = (tid & 31) << 2;
    const int tx   = tid & 15;
    const int ty   = tid >> 4;

    float acc[8][8];
#pragma unroll
    for (int i = 0; i < 8; i++)
#pragma unroll
        for (int j = 0; j < 8; j++) acc[i][j] = 0.f;

    const float* Aptr = A + (size_t)(bm + arow) * lda + k0 + akc;
    const float* Bptr = B + (size_t)(k0 + brow) * ldb + bn + bcol;
    const bool bok = (bn + bcol) < N;

    for (int kk = 0; kk < Kslice; kk += 8) {
        float4 av = *reinterpret_cast<const float4*>(Aptr);
        Aptr += 8;
        float4 bv = make_float4(0.f, 0.f, 0.f, 0.f);
        if (bok) bv = *reinterpret_cast<const float4*>(Bptr);
        Bptr += (size_t)8 * ldb;

        sA[akc + 0][arow] = av.x;
        sA[akc + 1][arow] = av.y;
        sA[akc + 2][arow] = av.z;
        sA[akc + 3][arow] = av.w;
        *reinterpret_cast<float4*>(&sB[brow][bcol]) = bv;
        __syncthreads();

#pragma unroll
        for (int p = 0; p < 8; p++) {
            float4 a0 = *reinterpret_cast<const float4*>(&sA[p][ty * 8]);
            float4 a1 = *reinterpret_cast<const float4*>(&sA[p][ty * 8 + 4]);
            float4 b0 = *reinterpret_cast<const float4*>(&sB[p][tx * 8]);
            float4 b1 = *reinterpret_cast<const float4*>(&sB[p][tx * 8 + 4]);
            float ra[8] = {a0.x, a0.y, a0.z, a0.w, a1.x, a1.y, a1.z, a1.w};
            float rb[8] = {b0.x, b0.y, b0.z, b0.w, b1.x, b1.y, b1.z, b1.w};
#pragma unroll
            for (int i = 0; i < 8; i++)
#pragma unroll
                for (int j = 0; j < 8; j++)
                    acc[i][j] = fmaf(ra[i], rb[j], acc[i][j]);
        }
        __syncthreads();
    }

#pragma unroll
    for (int i = 0; i < 8; i++) {
        const int row = bm + ty * 8 + i;
#pragma unroll
        for (int j = 0; j < 8; j++) {
            const int col = bn + tx * 8 + j;
            if (col < N) {
                float v = acc[i][j];
                if (EPI == 1) {
                    v += bias[col];
                    v = (v > 20.f) ? v : log1pf(expf(v));
                }
                C[(size_t)row * ldc + col] = v;
            }
        }
    }
}

// ---------------- depthwise causal conv (k=4) + SiLU ----------------
__global__ void conv_silu_kernel(const float* __restrict__ xz,
                                 const float* __restrict__ cw,
                                 const float* __restrict__ cb,
                                 float* __restrict__ xs)
{
    const int idx = blockIdx.x * blockDim.x + threadIdx.x;
    if (idx >= NTOK * DINNER) return;
    const int d   = idx & (DINNER - 1);
    const int tok = idx >> 11;                 // DINNER == 2048
    const int l   = tok & (SEQLEN - 1);

    float acc = cb[d];
    const float w0 = cw[d * 4 + 0];
    const float w1 = cw[d * 4 + 1];
    const float w2 = cw[d * 4 + 2];
    const float w3 = cw[d * 4 + 3];
    if (l >= 3) acc += w0 * xz[(size_t)(tok - 3) * (2 * DINNER) + d];
    if (l >= 2) acc += w1 * xz[(size_t)(tok - 2) * (2 * DINNER) + d];
    if (l >= 1) acc += w2 * xz[(size_t)(tok - 1) * (2 * DINNER) + d];
    acc += w3 * xz[(size_t)tok * (2 * DINNER) + d];

    xs[idx] = acc / (1.f + __expf(-acc));      // SiLU
}

// ---------------- split-K reduction (8 slices) ----------------
__global__ void reduce8_kernel(const float* __restrict__ part,
                               float* __restrict__ out, int len)
{
    const int i = blockIdx.x * blockDim.x + threadIdx.x;
    if (i >= len) return;
    float s = 0.f;
#pragma unroll
    for (int k = 0; k < 8; k++) s += part[(size_t)k * len + i];
    out[i] = s;
}

// ---------------- selective scan + skip + gate ----------------
__global__ void __launch_bounds__(128)
scan_kernel(const float* __restrict__ delta,
            const float* __restrict__ xs,
            const float* __restrict__ xp,
            const float* __restrict__ xz,
            const float* __restrict__ A_log,
            const float* __restrict__ Dpar,
            float* __restrict__ y)
{
    const int TT = 128;
    __shared__ float sB[TT][16];
    __shared__ float sC[TT][16];
    __shared__ float sd[TT][8];
    __shared__ float sx[TT][8];
    __shared__ float sz[TT][8];
    __shared__ float so[TT][8];

    const int b    = blockIdx.y;
    const int d0   = blockIdx.x * 8;
    const int tid  = threadIdx.x;
    const int lane = tid & 31;
    const int warp = tid >> 5;
    const int grp  = lane >> 4;
    const int n    = lane & 15;
    const int ch   = warp * 2 + grp;
    const int d    = d0 + ch;

    const float An = -__expf(A_log[d * DSTATE + n]);
    const float Dd = Dpar[d];
    float h = 0.f;

    for (int l0 = 0; l0 < SEQLEN; l0 += TT) {
        for (int i = tid; i < TT * 16; i += 128) {
            const int t = i >> 4, nn = i & 15;
            const float* row = xp + (size_t)(b * SEQLEN + l0 + t) * XPW;
            sB[t][nn] = row[DTRANK + nn];
            sC[t][nn] = row[DTRANK + DSTATE + nn];
        }
        for (int i = tid; i < TT * 8; i += 128) {
            const int t = i >> 3, c = i & 7;
            const size_t tok = (size_t)(b * SEQLEN + l0 + t);
            sd[t][c] = delta[tok * DINNER + d0 + c];
            sx[t][c] = xs[tok * DINNER + d0 + c];
            const float zz = xz[tok * (2 * DINNER) + DINNER + d0 + c];
            sz[t][c] = zz / (1.f + __expf(-zz));
        }
        __syncthreads();

#pragma unroll 4
        for (int t = 0; t < TT; t++) {
            const float dt = sd[t][ch];
            const float xt = sx[t][ch];
            const float dA = __expf(dt * An);
            h = fmaf(dA, h, dt * xt * sB[t][n]);
            float yv = h * sC[t][n];
            yv += __shfl_xor_sync(0xffffffffu, yv, 8);
            yv += __shfl_xor_sync(0xffffffffu, yv, 4);
            yv += __shfl_xor_sync(0xffffffffu, yv, 2);
            yv += __shfl_xor_sync(0xffffffffu, yv, 1);
            if (n == 0) so[t][ch] = (yv + Dd * xt) * sz[t][ch];
        }
        __syncthreads();

        for (int i = tid; i < TT * 8; i += 128) {
            const int t = i >> 3, c = i & 7;
            y[(size_t)(b * SEQLEN + l0 + t) * DINNER + d0 + c] = so[t][c];
        }
    }
}

// ---------------- launcher ----------------
extern "C" void kernel_launch(void* const* d_in, const int* in_sizes, int n_in,
                              void* d_out, int out_size)
{
    const float* x       = (const float*)d_in[0];
    const float* W_in    = (const float*)d_in[1];
    const float* conv_w  = (const float*)d_in[2];
    const float* conv_b  = (const float*)d_in[3];
    const float* W_xproj = (const float*)d_in[4];
    const float* W_dt    = (const float*)d_in[5];
    const float* b_dt    = (const float*)d_in[6];
    const float* A_log   = (const float*)d_in[7];
    const float* Dpar    = (const float*)d_in[8];
    const float* W_out   = (const float*)d_in[9];
    float* out = (float*)d_out;

    float *xz, *xs, *xp, *delta, *y, *part;
    cudaGetSymbolAddress((void**)&xz,    g_xz);
    cudaGetSymbolAddress((void**)&xs,    g_xs);
    cudaGetSymbolAddress((void**)&xp,    g_xp);
    cudaGetSymbolAddress((void**)&delta, g_delta);
    cudaGetSymbolAddress((void**)&y,     g_y);
    cudaGetSymbolAddress((void**)&part,  g_part);

    // G1: xz = x @ W_in  (4096 x 1024) @ (1024 x 4096)  -- TF32 tensor cores
    gemm_tf32<<<dim3((2 * DINNER) / 128, NTOK / 128), 256>>>(
        x, DMODEL, W_in, 2 * DINNER, xz, 2 * DINNER, DMODEL);

    // depthwise causal conv + SiLU -> xs
    conv_silu_kernel<<<(NTOK * DINNER) / 256, 256>>>(xz, conv_w, conv_b, xs);

    // G2 (split-K=8): xp = xs @ W_xproj   (4096 x 2048) @ (2048 x 96)
    sgemm128<0><<<dim3(1, NTOK / 128, 8), 256>>>(
        xs, DINNER, W_xproj, XPW, part, XPW,
        XPW, DINNER / 8, nullptr, (long long)NTOK * XPW);
    reduce8_kernel<<<(NTOK * XPW + 255) / 256, 256>>>(part, xp, NTOK * XPW);

    // G3: delta = softplus(xp[:, :64] @ W_dt + b_dt)   (4096 x 64) @ (64 x 2048)
    sgemm128<1><<<dim3(DINNER / 128, NTOK / 128, 1), 256>>>(
        xp, XPW, W_dt, DINNER, delta, DINNER,
        DINNER, DTRANK, b_dt, 0);

    // selective scan + D*x skip + silu(z) gate -> y
    scan_kernel<<<dim3(DINNER / 8, BATCH), 128>>>(
        delta, xs, xp, xz, A_log, Dpar, y);

    // G4: out = y @ W_out  (4096 x 2048) @ (2048 x 1024)  -- TF32 tensor cores
    gemm_tf32<<<dim3(DMODEL / 128, NTOK / 128), 256>>>(
        y, DINNER, W_out, DMODEL, out, DMODEL, DINNER);
}

// round 7
// speedup vs baseline: 1.6168x; 1.0657x over previous
#include <cuda_runtime.h>
#include <mma.h>
#include <math.h>
#include <stdint.h>

using namespace nvcuda;

// ---------------- problem constants ----------------
#define BATCH   2
#define SEQLEN  2048
#define DMODEL  1024
#define DINNER  2048
#define DSTATE  16
#define DTRANK  64
#define NTOK    (BATCH * SEQLEN)           // 4096
#define XPW     (DTRANK + 2 * DSTATE)      // 96

// ---------------- scratch (device globals; no cudaMalloc allowed) ----------------
__device__ float g_xz[NTOK * 2 * DINNER];        // (4096, 4096): xi | z
__device__ float g_xs[NTOK * DINNER];            // conv+silu output
__device__ float g_xp[NTOK * XPW];               // dt | B | C
__device__ float g_delta[NTOK * DINNER];         // softplus(dt @ W_dt + b_dt)
__device__ float g_y[NTOK * DINNER];             // gated scan output (tf32-rounded)
__device__ float g_part[8 * NTOK * XPW];         // split-K partials for G2
// tf32-pre-rounded GEMM operands
__device__ float g_xr[NTOK * DMODEL];            // x rounded
__device__ float g_winr[DMODEL * 2 * DINNER];    // W_in rounded
__device__ float g_woutr[DINNER * DMODEL];       // W_out rounded

// ---------------- helpers ----------------
__device__ __forceinline__ float round_tf32(float v) {
    uint32_t u;
    asm("cvt.rna.tf32.f32 %0, %1;" : "=r"(u) : "f"(v));
    return __uint_as_float(u);
}
__device__ __forceinline__ void cp_async16(void* smem_dst, const void* gmem_src) {
    unsigned saddr = (unsigned)__cvta_generic_to_shared(smem_dst);
    asm volatile("cp.async.cg.shared.global [%0], [%1], 16;\n" :: "r"(saddr), "l"(gmem_src));
}
__device__ __forceinline__ void cp_async_commit() {
    asm volatile("cp.async.commit_group;\n" ::);
}
__device__ __forceinline__ void cp_async_wait0() {
    asm volatile("cp.async.wait_group 0;\n" ::);
}

// ---------------- tf32 pre-round prepass (vectorized) ----------------
__global__ void round_tf32_kernel(const float4* __restrict__ in,
                                  float4* __restrict__ out, int n4)
{
    const int i = blockIdx.x * blockDim.x + threadIdx.x;
    if (i >= n4) return;
    float4 v = in[i];
    v.x = round_tf32(v.x);
    v.y = round_tf32(v.y);
    v.z = round_tf32(v.z);
    v.w = round_tf32(v.w);
    out[i] = v;
}

// ---------------- TF32 tensor-core GEMM: C(MxN) = A(MxK) @ B(KxN) ----------------
// Row-major A,B pre-rounded to tf32 bit patterns (no in-loop conversion).
// BM=BN=128, BK=16, 128 threads (4 warps), warp tile 64x64 (2x2 warp grid).
// M, N multiples of 128; K multiple of 16. cp.async double-buffered.
__global__ void __launch_bounds__(128, 2)
gemm_tf32(const float* __restrict__ A, int lda,
          const float* __restrict__ B, int ldb,
          float* __restrict__ C, int ldc, int K)
{
    __shared__ float sA[2][128][24];   // 24576 B
    __shared__ float sB[2][16][136];   // 17408 B

    const int bm  = blockIdx.y * 128;
    const int bn  = blockIdx.x * 128;
    const int tid = threadIdx.x;
    const int warp = tid >> 5;
    const int wr = warp >> 1;          // 0..1 -> 64 rows
    const int wc = warp & 1;           // 0..1 -> 64 cols

    wmma::fragment<wmma::accumulator, 16, 16, 8, float> acc[4][4];
#pragma unroll
    for (int i = 0; i < 4; i++)
#pragma unroll
        for (int j = 0; j < 4; j++) wmma::fill_fragment(acc[i][j], 0.f);

    // per-thread load coordinates (128 threads)
    const int a_row0 = tid >> 2;       // 0..31, stride 32, 4 iters -> 128 rows
    const int a_c4   = tid & 3;        // 4 float4 per row
    const int b_row0 = tid >> 5;       // 0..3, stride 4, 4 iters -> 16 rows
    const int b_c4   = tid & 31;       // 32 float4 per row

    const int T = K >> 4;

    // prologue: stage tile 0
    {
#pragma unroll
        for (int i = 0; i < 4; i++) {
            const int row = a_row0 + i * 32;
            cp_async16(&sA[0][row][a_c4 * 4],
                       A + (size_t)(bm + row) * lda + a_c4 * 4);
        }
#pragma unroll
        for (int i = 0; i < 4; i++) {
            const int row = b_row0 + i * 4;
            cp_async16(&sB[0][row][b_c4 * 4],
                       B + (size_t)row * ldb + bn + b_c4 * 4);
        }
        cp_async_commit();
    }

    for (int t = 0; t < T; t++) {
        const int s = t & 1;
        cp_async_wait0();
        __syncthreads();

        if (t + 1 < T) {
            const int kt = t + 1;
            const int s2 = s ^ 1;
#pragma unroll
            for (int i = 0; i < 4; i++) {
                const int row = a_row0 + i * 32;
                cp_async16(&sA[s2][row][a_c4 * 4],
                           A + (size_t)(bm + row) * lda + kt * 16 + a_c4 * 4);
            }
#pragma unroll
            for (int i = 0; i < 4; i++) {
                const int row = b_row0 + i * 4;
                cp_async16(&sB[s2][row][b_c4 * 4],
                           B + (size_t)(kt * 16 + row) * ldb + bn + b_c4 * 4);
            }
            cp_async_commit();
        }

#pragma unroll
        for (int ks = 0; ks < 2; ks++) {
            wmma::fragment<wmma::matrix_a, 16, 16, 8, wmma::precision::tf32, wmma::row_major> af[4];
            wmma::fragment<wmma::matrix_b, 16, 16, 8, wmma::precision::tf32, wmma::row_major> bf[4];
#pragma unroll
            for (int i = 0; i < 4; i++)
                wmma::load_matrix_sync(af[i], &sA[s][wr * 64 + i * 16][ks * 8], 24);
#pragma unroll
            for (int j = 0; j < 4; j++)
                wmma::load_matrix_sync(bf[j], &sB[s][ks * 8][wc * 64 + j * 16], 136);
#pragma unroll
            for (int i = 0; i < 4; i++)
#pragma unroll
                for (int j = 0; j < 4; j++)
                    wmma::mma_sync(acc[i][j], af[i], bf[j], acc[i][j]);
        }
        __syncthreads();
    }

#pragma unroll
    for (int i = 0; i < 4; i++)
#pragma unroll
        for (int j = 0; j < 4; j++) {
            float* dst = C + (size_t)(bm + wr * 64 + i * 16) * ldc
                           + bn + wc * 64 + j * 16;
            wmma::store_matrix_sync(dst, acc[i][j], ldc, wmma::mem_row_major);
        }
}

// ---------------- fp32 tiled GEMM (skinny G2 / G3) ----------------
template <int EPI>
__global__ void __launch_bounds__(256, 2)
sgemm128(const float* __restrict__ A, int lda,
         const float* __restrict__ B, int ldb,
         float* __restrict__ C, int ldc,
         int N, int Kslice,
         const float* __restrict__ bias,
         long long c_slice_stride)
{
    __shared__ float sA[8][128];
    __shared__ float sB[8][128];

    const int bm = blockIdx.y * 128;
    const int bn = blockIdx.x * 128;
    const int k0 = blockIdx.z * Kslice;
    C += (long long)blockIdx.z * c_slice_stride;

    const int tid  = threadIdx.x;
    const int arow = tid >> 1;
    const int akc  = (tid & 1) << 2;
    const int brow = tid >> 5;
    const int bcol = (tid & 31) << 2;
    const int tx   = tid & 15;
    const int ty   = tid >> 4;

    float acc[8][8];
#pragma unroll
    for (int i = 0; i < 8; i++)
#pragma unroll
        for (int j = 0; j < 8; j++) acc[i][j] = 0.f;

    const float* Aptr = A + (size_t)(bm + arow) * lda + k0 + akc;
    const float* Bptr = B + (size_t)(k0 + brow) * ldb + bn + bcol;
    const bool bok = (bn + bcol) < N;

    for (int kk = 0; kk < Kslice; kk += 8) {
        float4 av = *reinterpret_cast<const float4*>(Aptr);
        Aptr += 8;
        float4 bv = make_float4(0.f, 0.f, 0.f, 0.f);
        if (bok) bv = *reinterpret_cast<const float4*>(Bptr);
        Bptr += (size_t)8 * ldb;

        sA[akc + 0][arow] = av.x;
        sA[akc + 1][arow] = av.y;
        sA[akc + 2][arow] = av.z;
        sA[akc + 3][arow] = av.w;
        *reinterpret_cast<float4*>(&sB[brow][bcol]) = bv;
        __syncthreads();

#pragma unroll
        for (int p = 0; p < 8; p++) {
            float4 a0 = *reinterpret_cast<const float4*>(&sA[p][ty * 8]);
            float4 a1 = *reinterpret_cast<const float4*>(&sA[p][ty * 8 + 4]);
            float4 b0 = *reinterpret_cast<const float4*>(&sB[p][tx * 8]);
            float4 b1 = *reinterpret_cast<const float4*>(&sB[p][tx * 8 + 4]);
            float ra[8] = {a0.x, a0.y, a0.z, a0.w, a1.x, a1.y, a1.z, a1.w};
            float rb[8] = {b0.x, b0.y, b0.z, b0.w, b1.x, b1.y, b1.z, b1.w};
#pragma unroll
            for (int i = 0; i < 8; i++)
#pragma unroll
                for (int j = 0; j < 8; j++)
                    acc[i][j] = fmaf(ra[i], rb[j], acc[i][j]);
        }
        __syncthreads();
    }

#pragma unroll
    for (int i = 0; i < 8; i++) {
        const int row = bm + ty * 8 + i;
#pragma unroll
        for (int j = 0; j < 8; j++) {
            const int col = bn + tx * 8 + j;
            if (col < N) {
                float v = acc[i][j];
                if (EPI == 1) {
                    v += bias[col];
                    v = (v > 20.f) ? v : log1pf(expf(v));
                }
                C[(size_t)row * ldc + col] = v;
            }
        }
    }
}

// ---------------- depthwise causal conv (k=4) + SiLU ----------------
__global__ void conv_silu_kernel(const float* __restrict__ xz,
                                 const float* __restrict__ cw,
                                 const float* __restrict__ cb,
                                 float* __restrict__ xs)
{
    const int idx = blockIdx.x * blockDim.x + threadIdx.x;
    if (idx >= NTOK * DINNER) return;
    const int d   = idx & (DINNER - 1);
    const int tok = idx >> 11;
    const int l   = tok & (SEQLEN - 1);

    float acc = cb[d];
    const float w0 = cw[d * 4 + 0];
    const float w1 = cw[d * 4 + 1];
    const float w2 = cw[d * 4 + 2];
    const float w3 = cw[d * 4 + 3];
    if (l >= 3) acc += w0 * xz[(size_t)(tok - 3) * (2 * DINNER) + d];
    if (l >= 2) acc += w1 * xz[(size_t)(tok - 2) * (2 * DINNER) + d];
    if (l >= 1) acc += w2 * xz[(size_t)(tok - 1) * (2 * DINNER) + d];
    acc += w3 * xz[(size_t)tok * (2 * DINNER) + d];

    xs[idx] = acc / (1.f + __expf(-acc));
}

// ---------------- split-K reduction (8 slices) ----------------
__global__ void reduce8_kernel(const float* __restrict__ part,
                               float* __restrict__ out, int len)
{
    const int i = blockIdx.x * blockDim.x + threadIdx.x;
    if (i >= len) return;
    float s = 0.f;
#pragma unroll
    for (int k = 0; k < 8; k++) s += part[(size_t)k * len + i];
    out[i] = s;
}

// ---------------- selective scan + skip + gate (emits tf32-rounded y) ----------------
__global__ void __launch_bounds__(128)
scan_kernel(const float* __restrict__ delta,
            const float* __restrict__ xs,
            const float* __restrict__ xp,
            const float* __restrict__ xz,
            const float* __restrict__ A_log,
            const float* __restrict__ Dpar,
            float* __restrict__ y)
{
    const int TT = 128;
    __shared__ float sB[TT][16];
    __shared__ float sC[TT][16];
    __shared__ float sd[TT][8];
    __shared__ float sx[TT][8];
    __shared__ float sz[TT][8];
    __shared__ float so[TT][8];

    const int b    = blockIdx.y;
    const int d0   = blockIdx.x * 8;
    const int tid  = threadIdx.x;
    const int lane = tid & 31;
    const int warp = tid >> 5;
    const int grp  = lane >> 4;
    const int n    = lane & 15;
    const int ch   = warp * 2 + grp;
    const int d    = d0 + ch;

    const float An = -__expf(A_log[d * DSTATE + n]);
    const float Dd = Dpar[d];
    float h = 0.f;

    for (int l0 = 0; l0 < SEQLEN; l0 += TT) {
        for (int i = tid; i < TT * 16; i += 128) {
            const int t = i >> 4, nn = i & 15;
            const float* row = xp + (size_t)(b * SEQLEN + l0 + t) * XPW;
            sB[t][nn] = row[DTRANK + nn];
            sC[t][nn] = row[DTRANK + DSTATE + nn];
        }
        for (int i = tid; i < TT * 8; i += 128) {
            const int t = i >> 3, c = i & 7;
            const size_t tok = (size_t)(b * SEQLEN + l0 + t);
            sd[t][c] = delta[tok * DINNER + d0 + c];
            sx[t][c] = xs[tok * DINNER + d0 + c];
            const float zz = xz[tok * (2 * DINNER) + DINNER + d0 + c];
            sz[t][c] = zz / (1.f + __expf(-zz));
        }
        __syncthreads();

#pragma unroll 4
        for (int t = 0; t < TT; t++) {
            const float dt = sd[t][ch];
            const float xt = sx[t][ch];
            const float dA = __expf(dt * An);
            h = fmaf(dA, h, dt * xt * sB[t][n]);
            float yv = h * sC[t][n];
            yv += __shfl_xor_sync(0xffffffffu, yv, 8);
            yv += __shfl_xor_sync(0xffffffffu, yv, 4);
            yv += __shfl_xor_sync(0xffffffffu, yv, 2);
            yv += __shfl_xor_sync(0xffffffffu, yv, 1);
            if (n == 0) so[t][ch] = round_tf32((yv + Dd * xt) * sz[t][ch]);
        }
        __syncthreads();

        for (int i = tid; i < TT * 8; i += 128) {
            const int t = i >> 3, c = i & 7;
            y[(size_t)(b * SEQLEN + l0 + t) * DINNER + d0 + c] = so[t][c];
        }
    }
}

// ---------------- launcher ----------------
extern "C" void kernel_launch(void* const* d_in, const int* in_sizes, int n_in,
                              void* d_out, int out_size)
{
    const float* x       = (const float*)d_in[0];
    const float* W_in    = (const float*)d_in[1];
    const float* conv_w  = (const float*)d_in[2];
    const float* conv_b  = (const float*)d_in[3];
    const float* W_xproj = (const float*)d_in[4];
    const float* W_dt    = (const float*)d_in[5];
    const float* b_dt    = (const float*)d_in[6];
    const float* A_log   = (const float*)d_in[7];
    const float* Dpar    = (const float*)d_in[8];
    const float* W_out   = (const float*)d_in[9];
    float* out = (float*)d_out;

    float *xz, *xs, *xp, *delta, *y, *part, *xr, *winr, *woutr;
    cudaGetSymbolAddress((void**)&xz,    g_xz);
    cudaGetSymbolAddress((void**)&xs,    g_xs);
    cudaGetSymbolAddress((void**)&xp,    g_xp);
    cudaGetSymbolAddress((void**)&delta, g_delta);
    cudaGetSymbolAddress((void**)&y,     g_y);
    cudaGetSymbolAddress((void**)&part,  g_part);
    cudaGetSymbolAddress((void**)&xr,    g_xr);
    cudaGetSymbolAddress((void**)&winr,  g_winr);
    cudaGetSymbolAddress((void**)&woutr, g_woutr);

    // tf32 pre-round prepass (x, W_in, W_out)
    {
        const int n1 = NTOK * DMODEL / 4;
        round_tf32_kernel<<<(n1 + 255) / 256, 256>>>((const float4*)x, (float4*)xr, n1);
        const int n2 = DMODEL * 2 * DINNER / 4;
        round_tf32_kernel<<<(n2 + 255) / 256, 256>>>((const float4*)W_in, (float4*)winr, n2);
        const int n3 = DINNER * DMODEL / 4;
        round_tf32_kernel<<<(n3 + 255) / 256, 256>>>((const float4*)W_out, (float4*)woutr, n3);
    }

    // G1: xz = x @ W_in  (4096 x 1024) @ (1024 x 4096)  -- TF32 TC, pre-rounded
    gemm_tf32<<<dim3((2 * DINNER) / 128, NTOK / 128), 128>>>(
        xr, DMODEL, winr, 2 * DINNER, xz, 2 * DINNER, DMODEL);

    // depthwise causal conv + SiLU -> xs
    conv_silu_kernel<<<(NTOK * DINNER) / 256, 256>>>(xz, conv_w, conv_b, xs);

    // G2 (split-K=8): xp = xs @ W_xproj   (4096 x 2048) @ (2048 x 96)
    sgemm128<0><<<dim3(1, NTOK / 128, 8), 256>>>(
        xs, DINNER, W_xproj, XPW, part, XPW,
        XPW, DINNER / 8, nullptr, (long long)NTOK * XPW);
    reduce8_kernel<<<(NTOK * XPW + 255) / 256, 256>>>(part, xp, NTOK * XPW);

    // G3: delta = softplus(xp[:, :64] @ W_dt + b_dt)   (4096 x 64) @ (64 x 2048)
    sgemm128<1><<<dim3(DINNER / 128, NTOK / 128, 1), 256>>>(
        xp, XPW, W_dt, DINNER, delta, DINNER,
        DINNER, DTRANK, b_dt, 0);

    // selective scan + D*x skip + silu(z) gate -> y (tf32-rounded)
    scan_kernel<<<dim3(DINNER / 8, BATCH), 128>>>(
        delta, xs, xp, xz, A_log, Dpar, y);

    // G4: out = y @ W_out  (4096 x 2048) @ (2048 x 1024)  -- TF32 TC, pre-rounded
    gemm_tf32<<<dim3(DMODEL / 128, NTOK / 128), 128>>>(
        y, DINNER, woutr, DMODEL, out, DMODEL, DINNER);
}